// round 9
// baseline (speedup 1.0000x reference)
#include <cuda_runtime.h>

// SymmetryConstraint: block-per-batch (512 thr, 1 pt/thread) closed-form
// moment reduction, deterministic fixed-point global accumulation,
// fence-free acq_rel tail.
//
// Per (batch, class k in {0,1,2}) with m points, u = x-0.5:
//   pair-loss sum = (m-2)*Su2 + Su^2 + m*Sy2 - Sy^2   (>= 0)
//   pair count    = m(m-1)/2
// result = total_loss / max(total_count, 1)

#define BATCH   256
#define NPTS    512
#define THREADS 512
#define NWARP   (THREADS / 32)   // 16

__device__ unsigned long long g_loss_fix = 0ULL;
__device__ unsigned long long g_cnt_fix  = 0ULL;
__device__ unsigned int       g_done     = 0u;

#define LOSS_SCALE 33554432.0f   // 2^25

__global__ __launch_bounds__(THREADS)
void symmetry_kernel(const float2* __restrict__ kp2,
                     const int*    __restrict__ cls,
                     float* __restrict__ out)
{
    const int b    = blockIdx.x;
    const int tid  = threadIdx.x;
    const int lane = tid & 31;
    const int wid  = tid >> 5;

    // one point per thread
    float2 p  = kp2[(size_t)b * NPTS + tid];
    int    ci = cls[(size_t)b * NPTS + tid];

    const float u = p.x - 0.5f;
    const float y = p.y;

    // per-class counts: ballot + popc (every lane gets the warp count)
    int m0 = __popc(__ballot_sync(0xffffffffu, ci == 0));
    int m1 = __popc(__ballot_sync(0xffffffffu, ci == 1));
    int m2 = __popc(__ballot_sync(0xffffffffu, ci == 2));

    // 3 classes x {Su, Su2, Sy, Sy2}
    float fa[12];
#pragma unroll
    for (int k = 0; k < 3; k++) {
        float w = (ci == k) ? 1.f : 0.f;
        fa[k * 4 + 0] = w * u;
        fa[k * 4 + 1] = w * u * u;
        fa[k * 4 + 2] = w * y;
        fa[k * 4 + 3] = w * y * y;
    }

    // warp reduce 12 independent floats (pipelined shuffle stages)
#pragma unroll
    for (int off = 16; off; off >>= 1) {
#pragma unroll
        for (int i = 0; i < 12; i++)
            fa[i] += __shfl_down_sync(0xffffffffu, fa[i], off);
    }

    __shared__ float s_mom[NWARP][16];   // 15 used, padded row
    if (lane == 0) {
#pragma unroll
        for (int i = 0; i < 12; i++) s_mom[wid][i] = fa[i];
        s_mom[wid][12] = (float)m0;
        s_mom[wid][13] = (float)m1;
        s_mom[wid][14] = (float)m2;
    }
    __syncthreads();

    if (wid == 0) {
        // lanes 0..14 each sum one quantity across 16 warps (parallel)
        float s = 0.f;
        if (lane < 15) {
#pragma unroll
            for (int w = 0; w < NWARP; w++) s += s_mom[w][lane];
        }
        float tot[15];
#pragma unroll
        for (int i = 0; i < 15; i++)
            tot[i] = __shfl_sync(0xffffffffu, s, i);

        if (lane == 0) {
            float loss = 0.f, cnt = 0.f;
#pragma unroll
            for (int k = 0; k < 3; k++) {
                float su  = tot[k * 4 + 0];
                float su2 = tot[k * 4 + 1];
                float sy  = tot[k * 4 + 2];
                float sy2 = tot[k * 4 + 3];
                float m   = tot[12 + k];
                loss += (m - 2.f) * su2 + su * su + m * sy2 - sy * sy;
                cnt  += 0.5f * m * (m - 1.f);   // exact: m integer < 2^10
            }
            loss = fmaxf(loss, 0.f);

            // deterministic order-independent integer accumulation (relaxed)
            unsigned long long lfix = (unsigned long long)(loss * LOSS_SCALE + 0.5f);
            unsigned long long cfix = (unsigned long long)(cnt + 0.5f);
            atomicAdd(&g_loss_fix, lfix);
            atomicAdd(&g_cnt_fix,  cfix);

            // acq_rel counter: release orders our adds; acquire on the read
            // side makes all 256 blocks' adds visible to the finisher.
            unsigned int prev;
            asm volatile("atom.add.acq_rel.gpu.global.u32 %0, [%1], 1;"
                         : "=r"(prev) : "l"(&g_done) : "memory");

            if (prev == BATCH - 1) {
                unsigned long long L, C;
                asm volatile("ld.acquire.gpu.global.u64 %0, [%1];"
                             : "=l"(L) : "l"(&g_loss_fix) : "memory");
                asm volatile("ld.acquire.gpu.global.u64 %0, [%1];"
                             : "=l"(C) : "l"(&g_cnt_fix) : "memory");
                double total = (double)L * (1.0 / 33554432.0);
                double denom = (C > 0ULL) ? (double)C : 1.0;
                out[0] = (float)(total / denom);
                // reset for next graph replay (ordered by kernel boundary)
                g_loss_fix = 0ULL;
                g_cnt_fix  = 0ULL;
                g_done     = 0u;
            }
        }
    }
}

extern "C" void kernel_launch(void* const* d_in, const int* in_sizes, int n_in,
                              void* d_out, int out_size)
{
    const float2* kp2 = (const float2*)d_in[0];  // [256, 512, 2] f32
    const int*    cls = (const int*)d_in[1];     // [256, 512] i32
    float*        out = (float*)d_out;           // [1] f32
    symmetry_kernel<<<BATCH, THREADS>>>(kp2, cls, out);
}

// round 10
// speedup vs baseline: 1.0037x; 1.0037x over previous
#include <cuda_runtime.h>

// SymmetryConstraint: 2 batches per block (independent half-blocks of 8 warps),
// closed-form moment reduction, deterministic fixed-point accumulation,
// fence-free acq_rel tail.
//
// Per (batch, class k in {0,1,2}) with m points, u = x-0.5:
//   pair-loss sum = (m-2)*Su2 + Su^2 + m*Sy2 - Sy^2   (>= 0)
//   pair count    = m(m-1)/2
// result = total_loss / max(total_count, 1)

#define BATCH    256
#define NPTS     512
#define THREADS  512
#define BLOCKS   (BATCH / 2)      // 128
#define NWARP    (THREADS / 32)   // 16, 8 per half-block

__device__ unsigned long long g_loss_fix = 0ULL;
__device__ unsigned long long g_cnt_fix  = 0ULL;
__device__ unsigned int       g_done     = 0u;

#define LOSS_SCALE 33554432.0f   // 2^25

__global__ __launch_bounds__(THREADS)
void symmetry_kernel(const float4* __restrict__ kp4,
                     const int2*   __restrict__ cls2,
                     float* __restrict__ out)
{
    const int tid   = threadIdx.x;
    const int lane  = tid & 31;
    const int wid   = tid >> 5;          // 0..15
    const int half  = wid >> 3;          // 0 or 1
    const int tid_h = tid & 255;         // thread id within half-block
    const int b     = blockIdx.x * 2 + half;

    // 256 float4 (2 pts each) + 256 int2 per batch; one of each per thread.
    float4 p = kp4 [(size_t)b * (NPTS / 2) + tid_h];
    int2   c = cls2[(size_t)b * (NPTS / 2) + tid_h];

    // 3 classes x {Su, Su2, Sy, Sy2} float; counts int.
    float fa[12];
#pragma unroll
    for (int i = 0; i < 12; i++) fa[i] = 0.f;
    int m0 = 0, m1 = 0, m2 = 0;

    float ux[2] = { p.x - 0.5f, p.z - 0.5f };
    float yy[2] = { p.y,        p.w        };
    int   cc[2] = { c.x,        c.y        };

#pragma unroll
    for (int t = 0; t < 2; t++) {
        float u = ux[t], y = yy[t];
        int ci = cc[t];
        m0 += (ci == 0);
        m1 += (ci == 1);
        m2 += (ci == 2);
#pragma unroll
        for (int k = 0; k < 3; k++) {
            float w = (ci == k) ? 1.f : 0.f;
            fa[k * 4 + 0] += w * u;
            fa[k * 4 + 1] += w * u * u;
            fa[k * 4 + 2] += w * y;
            fa[k * 4 + 3] += w * y * y;
        }
    }

    // warp reduce: 12 floats via pipelined shuffles, 3 ints via REDUX
#pragma unroll
    for (int off = 16; off; off >>= 1) {
#pragma unroll
        for (int i = 0; i < 12; i++)
            fa[i] += __shfl_down_sync(0xffffffffu, fa[i], off);
    }
    m0 = __reduce_add_sync(0xffffffffu, m0);
    m1 = __reduce_add_sync(0xffffffffu, m1);
    m2 = __reduce_add_sync(0xffffffffu, m2);

    __shared__ float s_mom[NWARP][16];   // 15 used, padded row
    if (lane == 0) {
#pragma unroll
        for (int i = 0; i < 12; i++) s_mom[wid][i] = fa[i];
        s_mom[wid][12] = (float)m0;
        s_mom[wid][13] = (float)m1;
        s_mom[wid][14] = (float)m2;
    }
    __syncthreads();

    // warp 0 finishes batch 2B, warp 8 finishes batch 2B+1 (independent)
    if ((wid & 7) == 0) {
        const int base = half * 8;       // this half's warp rows
        float s = 0.f;
        if (lane < 15) {
#pragma unroll
            for (int w = 0; w < 8; w++) s += s_mom[base + w][lane];
        }
        float tot[15];
#pragma unroll
        for (int i = 0; i < 15; i++)
            tot[i] = __shfl_sync(0xffffffffu, s, i);

        if (lane == 0) {
            float loss = 0.f, cnt = 0.f;
#pragma unroll
            for (int k = 0; k < 3; k++) {
                float su  = tot[k * 4 + 0];
                float su2 = tot[k * 4 + 1];
                float sy  = tot[k * 4 + 2];
                float sy2 = tot[k * 4 + 3];
                float m   = tot[12 + k];
                loss += (m - 2.f) * su2 + su * su + m * sy2 - sy * sy;
                cnt  += 0.5f * m * (m - 1.f);   // exact: m integer < 2^10
            }
            loss = fmaxf(loss, 0.f);

            // deterministic order-independent integer accumulation (relaxed)
            unsigned long long lfix = (unsigned long long)(loss * LOSS_SCALE + 0.5f);
            unsigned long long cfix = (unsigned long long)(cnt + 0.5f);
            atomicAdd(&g_loss_fix, lfix);
            atomicAdd(&g_cnt_fix,  cfix);

            // acq_rel counter: release orders our adds; acquire makes all
            // 256 contributions visible to whoever sees prev == BATCH-1.
            unsigned int prev;
            asm volatile("atom.add.acq_rel.gpu.global.u32 %0, [%1], 1;"
                         : "=r"(prev) : "l"(&g_done) : "memory");

            if (prev == BATCH - 1) {
                unsigned long long L, C;
                asm volatile("ld.acquire.gpu.global.u64 %0, [%1];"
                             : "=l"(L) : "l"(&g_loss_fix) : "memory");
                asm volatile("ld.acquire.gpu.global.u64 %0, [%1];"
                             : "=l"(C) : "l"(&g_cnt_fix) : "memory");
                double total = (double)L * (1.0 / 33554432.0);
                double denom = (C > 0ULL) ? (double)C : 1.0;
                out[0] = (float)(total / denom);
                // reset for next graph replay (ordered by kernel boundary)
                g_loss_fix = 0ULL;
                g_cnt_fix  = 0ULL;
                g_done     = 0u;
            }
        }
    }
}

extern "C" void kernel_launch(void* const* d_in, const int* in_sizes, int n_in,
                              void* d_out, int out_size)
{
    const float4* kp4  = (const float4*)d_in[0];  // [256, 512, 2] f32
    const int2*   cls2 = (const int2*)d_in[1];    // [256, 512] i32
    float*        out  = (float*)d_out;           // [1] f32
    symmetry_kernel<<<BLOCKS, THREADS>>>(kp4, cls2, out);
}